// round 10
// baseline (speedup 1.0000x reference)
#include <cuda_runtime.h>
#include <cuda_bf16.h>
#include <cstdint>

// ColBERT MaxSim via mma.sync bf16 HMMA — single persistent kernel, 2 CTAs/SM.
//   scores[b,c] = sum_n max_s dot(qs[b,n,:], ps[c,s,:])
// qs: (64,32,128) fp32, ps: (64,1024,128) fp32, out: (64,64) fp32.
//
// grid (64 c, 4 quarter) = 256 CTAs, 2 CTAs/SM co-resident: one CTA's staging,
// barriers and epilogues hide under the other CTA's HMMA stream.
// A fragments stay hoisted (af[2][8][4]); single A smem buffer (cp.async latency
// covered by the co-resident CTA); <=128 regs via __launch_bounds__(256,2).

#define DIM 128
#define ROWB 272          // padded bf16 row: 136 bf16 = 272 B -> ldmatrix conflict-free
#define QTOK 256          // doc tokens per CTA
#define QROWS 2048        // 64 b * 32 n
#define NTILES 16
#define NTHREADS 256

#define P_OFF 0
#define A_OFF  (QTOK * ROWB)                // 69632
#define SM_TOTAL (A_OFF + 128 * ROWB)       // 104448 -> 2 CTAs/SM

__device__ float g_part[64 * 4 * QROWS];       // [c][quarter][qrow]
__device__ __nv_bfloat16 g_qbf[QROWS * DIM];
__device__ unsigned int g_qctr;        // monotonic across graph replays
__device__ unsigned int g_cctr[64];    // monotonic; (old&3)==3 -> last of 4

__device__ __forceinline__ uint32_t smem_u32(const void* p) {
    uint32_t a;
    asm("{ .reg .u64 t; cvta.to.shared.u64 t, %1; cvt.u32.u64 %0, t; }" : "=r"(a) : "l"(p));
    return a;
}

#define LDSM_X4(r0, r1, r2, r3, addr) \
    asm volatile("ldmatrix.sync.aligned.m8n8.x4.shared.b16 {%0,%1,%2,%3}, [%4];" \
                 : "=r"(r0), "=r"(r1), "=r"(r2), "=r"(r3) : "r"(addr))

#define MMA_16816(d, a, b0r, b1r) \
    asm volatile("mma.sync.aligned.m16n8k16.row.col.f32.bf16.bf16.f32 " \
                 "{%0,%1,%2,%3}, {%4,%5,%6,%7}, {%8,%9}, {%0,%1,%2,%3};" \
                 : "+f"((d)[0]), "+f"((d)[1]), "+f"((d)[2]), "+f"((d)[3]) \
                 : "r"((a)[0]), "r"((a)[1]), "r"((a)[2]), "r"((a)[3]), \
                   "r"(b0r), "r"(b1r))

#define CP_ASYNC16(dst, src) \
    asm volatile("cp.async.cg.shared.global [%0], [%1], 16;" :: "r"(dst), "l"(src) : "memory")
#define CP_COMMIT()  asm volatile("cp.async.commit_group;" ::: "memory")
#define CP_WAIT0()   asm volatile("cp.async.wait_group 0;" ::: "memory")

// Convert a ROWS x 128 fp32 row-major tile into bf16 padded smem (stride ROWB bytes).
template<int ROWS>
__device__ __forceinline__ void stage_bf16(char* sm_dst, const float* __restrict__ src) {
    const int tid = threadIdx.x;
    #pragma unroll 4
    for (int i = tid; i < ROWS * 16; i += NTHREADS) {
        int row = i >> 4;
        int c8  = (i & 15) << 3;
        const float4* s4 = reinterpret_cast<const float4*>(src + row * DIM + c8);
        float4 v0 = s4[0];
        float4 v1 = s4[1];
        __nv_bfloat162 b0 = __floats2bfloat162_rn(v0.x, v0.y);
        __nv_bfloat162 b1 = __floats2bfloat162_rn(v0.z, v0.w);
        __nv_bfloat162 b2 = __floats2bfloat162_rn(v1.x, v1.y);
        __nv_bfloat162 b3 = __floats2bfloat162_rn(v1.z, v1.w);
        uint4 packed;
        packed.x = *reinterpret_cast<uint32_t*>(&b0);
        packed.y = *reinterpret_cast<uint32_t*>(&b1);
        packed.z = *reinterpret_cast<uint32_t*>(&b2);
        packed.w = *reinterpret_cast<uint32_t*>(&b3);
        *reinterpret_cast<uint4*>(sm_dst + row * ROWB + c8 * 2) = packed;
    }
}

// Async-stage a 128 x 128 bf16 tile (contiguous 256B rows) into padded smem.
__device__ __forceinline__ void stage_A_async(uint32_t a_dst, const __nv_bfloat16* src) {
    const int tid = threadIdx.x;
    #pragma unroll
    for (int i = tid; i < 128 * 16; i += NTHREADS) {
        int row = i >> 4;
        int cb  = (i & 15) << 4;
        CP_ASYNC16(a_dst + row * ROWB + cb,
                   reinterpret_cast<const char*>(src) + row * 256 + cb);
    }
}

__global__ __launch_bounds__(NTHREADS, 2)
void colbert_fused_kernel(const float* __restrict__ qs,
                          const float* __restrict__ ps,
                          float* __restrict__ out) {
    extern __shared__ char sm[];
    __shared__ float s_red[2][128];
    __shared__ unsigned int s_target;
    __shared__ int s_last;

    const int c = blockIdx.x;
    const int qq = blockIdx.y;          // token quarter
    const int cta = c * 4 + qq;         // 0..255
    const int tid = threadIdx.x;
    const int lane = tid & 31;
    const int wid = tid >> 5;
    const int wr = wid & 3;             // row group: rows [wr*32, +32)
    const int wc = wid >> 2;            // col half within each 64-col nb block

    const uint32_t p_base = smem_u32(sm) + P_OFF;
    const uint32_t a_base = smem_u32(sm) + A_OFF;

    // ── Phase A: convert this CTA's 8-row slice of qs to bf16 global. ──
    if (tid < 128) {
        const float4* s4 = reinterpret_cast<const float4*>(qs) + ((size_t)cta * 128 + tid) * 2;
        float4 v0 = s4[0];
        float4 v1 = s4[1];
        __nv_bfloat162 b0 = __floats2bfloat162_rn(v0.x, v0.y);
        __nv_bfloat162 b1 = __floats2bfloat162_rn(v0.z, v0.w);
        __nv_bfloat162 b2 = __floats2bfloat162_rn(v1.x, v1.y);
        __nv_bfloat162 b3 = __floats2bfloat162_rn(v1.z, v1.w);
        uint4 packed;
        packed.x = *reinterpret_cast<uint32_t*>(&b0);
        packed.y = *reinterpret_cast<uint32_t*>(&b1);
        packed.z = *reinterpret_cast<uint32_t*>(&b2);
        packed.w = *reinterpret_cast<uint32_t*>(&b3);
        reinterpret_cast<uint4*>(g_qbf)[(size_t)cta * 128 + tid] = packed;
    }
    __syncthreads();
    if (tid == 0) {
        __threadfence();
        unsigned int old = atomicAdd(&g_qctr, 1u);
        s_target = (old / 256u) * 256u + 256u;   // epoch-safe across graph replays
    }

    // ── Phase B: stage the 256-token p quarter (fp32 -> bf16, disjoint per CTA). ──
    const float* pg = ps + ((size_t)c * 1024 + (size_t)qq * QTOK) * DIM;
    stage_bf16<QTOK>(sm + P_OFF, pg);

    __syncthreads();
    if (tid == 0) {
        while (atomicAdd(&g_qctr, 0u) < s_target) { }
        __threadfence();
    }
    __syncthreads();

    stage_A_async(a_base, g_qbf);
    CP_COMMIT();

    // ldmatrix lane addressing.
    const uint32_t a_lane_off = (uint32_t)((lane & 15) * ROWB + (lane >> 4) * 16);
    const int bgrp = lane >> 3;
    const uint32_t b_lane_off = (uint32_t)(((bgrp >> 1) * 8 + (lane & 7)) * ROWB + (bgrp & 1) * 16);

    // ── Phase C: 16 tiles of 128 q-rows vs 256 tokens. ──
    #pragma unroll 1
    for (int t = 0; t < NTILES; t++) {
        CP_WAIT0();
        __syncthreads();   // A[t] visible to all warps

        // Hoist A fragments: 2 m-tiles x 8 k-steps x 4 regs.
        uint32_t af[2][8][4];
        #pragma unroll
        for (int mt = 0; mt < 2; mt++) {
            #pragma unroll
            for (int ks = 0; ks < 8; ks++) {
                uint32_t addr = a_base + (uint32_t)((wr * 32 + mt * 16) * ROWB + ks * 32)
                              + a_lane_off;
                LDSM_X4(af[mt][ks][0], af[mt][ks][1], af[mt][ks][2], af[mt][ks][3], addr);
            }
        }
        __syncthreads();   // all warps hoisted -> A buffer reusable

        if (t + 1 < NTILES)
            stage_A_async(a_base, g_qbf + (size_t)(t + 1) * 128 * DIM);
        CP_COMMIT();

        float rm[2][2] = {{-3.0e38f, -3.0e38f}, {-3.0e38f, -3.0e38f}};

        #pragma unroll 1
        for (int nb = 0; nb < 4; nb++) {
            const int col0 = nb * 64 + wc * 32;
            float acc[2][4][4];
            #pragma unroll
            for (int mt = 0; mt < 2; mt++)
                #pragma unroll
                for (int nt = 0; nt < 4; nt++)
                    #pragma unroll
                    for (int i = 0; i < 4; i++) acc[mt][nt][i] = 0.0f;

            #pragma unroll
            for (int ks = 0; ks < 8; ks++) {
                uint32_t b0a = p_base + (uint32_t)(col0 * ROWB + ks * 32) + b_lane_off;
                uint32_t r0, r1, r2, r3, r4, r5, r6, r7;
                LDSM_X4(r0, r1, r2, r3, b0a);
                LDSM_X4(r4, r5, r6, r7, b0a + 16 * ROWB);
                #pragma unroll
                for (int mt = 0; mt < 2; mt++) {
                    MMA_16816(acc[mt][0], af[mt][ks], r0, r1);
                    MMA_16816(acc[mt][1], af[mt][ks], r2, r3);
                    MMA_16816(acc[mt][2], af[mt][ks], r4, r5);
                    MMA_16816(acc[mt][3], af[mt][ks], r6, r7);
                }
            }

            #pragma unroll
            for (int mt = 0; mt < 2; mt++)
                #pragma unroll
                for (int nt = 0; nt < 4; nt++) {
                    rm[mt][0] = fmaxf(rm[mt][0], fmaxf(acc[mt][nt][0], acc[mt][nt][1]));
                    rm[mt][1] = fmaxf(rm[mt][1], fmaxf(acc[mt][nt][2], acc[mt][nt][3]));
                }
        }

        // Reduce across the 4 lanes sharing each row; combine wc groups via smem.
        #pragma unroll
        for (int mt = 0; mt < 2; mt++)
            #pragma unroll
            for (int h = 0; h < 2; h++) {
                float v = rm[mt][h];
                v = fmaxf(v, __shfl_xor_sync(0xffffffffu, v, 1));
                v = fmaxf(v, __shfl_xor_sync(0xffffffffu, v, 2));
                if ((lane & 3) == 0)
                    s_red[wc][wr * 32 + mt * 16 + h * 8 + (lane >> 2)] = v;
            }
        __syncthreads();
        if (tid < 128) {
            float v = fmaxf(s_red[0][tid], s_red[1][tid]);
            g_part[((size_t)c * 4 + qq) * QROWS + t * 128 + tid] = v;
        }
    }

    // ── Phase D: last CTA of this c combines 4 quarters + sums over n. ──
    __syncthreads();
    if (tid == 0) {
        __threadfence();
        unsigned int old = atomicAdd(&g_cctr[c], 1u);
        s_last = ((old & 3u) == 3u);
    }
    __syncthreads();
    if (s_last) {
        if (tid == 0) __threadfence();
        __syncthreads();
        const float* p0 = g_part + (size_t)(c * 4 + 0) * QROWS;
        const float* p1 = g_part + (size_t)(c * 4 + 1) * QROWS;
        const float* p2 = g_part + (size_t)(c * 4 + 2) * QROWS;
        const float* p3 = g_part + (size_t)(c * 4 + 3) * QROWS;
        #pragma unroll
        for (int bb = 0; bb < 8; bb++) {
            int b = wid + bb * 8;
            int qrow = b * 32 + lane;
            float m = fmaxf(fmaxf(p0[qrow], p1[qrow]), fmaxf(p2[qrow], p3[qrow]));
            #pragma unroll
            for (int o = 16; o; o >>= 1) m += __shfl_xor_sync(0xffffffffu, m, o);
            if (lane == 0) out[b * 64 + c] = m;
        }
    }
}

extern "C" void kernel_launch(void* const* d_in, const int* in_sizes, int n_in,
                              void* d_out, int out_size) {
    const float* qs = (const float*)d_in[0];   // (64, 32, 128)
    const float* ps = (const float*)d_in[1];   // (64, 1024, 128)
    float* out = (float*)d_out;                // (64, 64)

    cudaFuncSetAttribute(colbert_fused_kernel,
                         cudaFuncAttributeMaxDynamicSharedMemorySize, SM_TOTAL);
    dim3 grid(64, 4);
    colbert_fused_kernel<<<grid, NTHREADS, SM_TOTAL>>>(qs, ps, out);
}

// round 11
// speedup vs baseline: 1.0847x; 1.0847x over previous
#include <cuda_runtime.h>
#include <cuda_bf16.h>
#include <cstdint>

// ColBERT MaxSim via mma.sync bf16 HMMA — single persistent kernel.
//   scores[b,c] = sum_n max_s dot(qs[b,n,:], ps[c,s,:])
// qs: (64,32,128) fp32, ps: (64,1024,128) fp32, out: (64,64) fp32.
//
// grid (64 c, 2 half) = 128 CTAs, 1 CTA/SM, all resident. R9 base
// + per-warp partial maxes written straight to global (no per-tile epilogue
//   barrier / smem combine): exactly one __syncthreads per tile.

#define DIM 128
#define ROWB 272          // padded bf16 row: 136 bf16 = 272 B -> ldmatrix conflict-free
#define HALF_TOK 512
#define QROWS 2048        // 64 b * 32 n
#define NTILES 16
#define NTHREADS 256

#define P_OFF 0
#define A_OFF  (HALF_TOK * ROWB)            // 139264
#define A_SZ   (128 * ROWB)                 // 34816
#define SM_TOTAL (A_OFF + 2 * A_SZ)         // 208896

__device__ float g_part[64 * 2 * 2 * QROWS];   // [c][half][wc][qrow]
__device__ __nv_bfloat16 g_qbf[QROWS * DIM];
__device__ unsigned int g_qctr;        // monotonic across graph replays
__device__ unsigned int g_cctr[64];    // monotonic, parity = last of pair

__device__ __forceinline__ uint32_t smem_u32(const void* p) {
    uint32_t a;
    asm("{ .reg .u64 t; cvta.to.shared.u64 t, %1; cvt.u32.u64 %0, t; }" : "=r"(a) : "l"(p));
    return a;
}

#define LDSM_X4(r0, r1, r2, r3, addr) \
    asm volatile("ldmatrix.sync.aligned.m8n8.x4.shared.b16 {%0,%1,%2,%3}, [%4];" \
                 : "=r"(r0), "=r"(r1), "=r"(r2), "=r"(r3) : "r"(addr))

#define MMA_16816(d, a, b0r, b1r) \
    asm volatile("mma.sync.aligned.m16n8k16.row.col.f32.bf16.bf16.f32 " \
                 "{%0,%1,%2,%3}, {%4,%5,%6,%7}, {%8,%9}, {%0,%1,%2,%3};" \
                 : "+f"((d)[0]), "+f"((d)[1]), "+f"((d)[2]), "+f"((d)[3]) \
                 : "r"((a)[0]), "r"((a)[1]), "r"((a)[2]), "r"((a)[3]), \
                   "r"(b0r), "r"(b1r))

#define CP_ASYNC16(dst, src) \
    asm volatile("cp.async.cg.shared.global [%0], [%1], 16;" :: "r"(dst), "l"(src) : "memory")
#define CP_COMMIT()  asm volatile("cp.async.commit_group;" ::: "memory")
#define CP_WAIT0()   asm volatile("cp.async.wait_group 0;" ::: "memory")

// Convert a ROWS x 128 fp32 row-major tile into bf16 padded smem (stride ROWB bytes).
template<int ROWS>
__device__ __forceinline__ void stage_bf16(char* sm_dst, const float* __restrict__ src) {
    const int tid = threadIdx.x;
    #pragma unroll 4
    for (int i = tid; i < ROWS * 16; i += NTHREADS) {
        int row = i >> 4;
        int c8  = (i & 15) << 3;
        const float4* s4 = reinterpret_cast<const float4*>(src + row * DIM + c8);
        float4 v0 = s4[0];
        float4 v1 = s4[1];
        __nv_bfloat162 b0 = __floats2bfloat162_rn(v0.x, v0.y);
        __nv_bfloat162 b1 = __floats2bfloat162_rn(v0.z, v0.w);
        __nv_bfloat162 b2 = __floats2bfloat162_rn(v1.x, v1.y);
        __nv_bfloat162 b3 = __floats2bfloat162_rn(v1.z, v1.w);
        uint4 packed;
        packed.x = *reinterpret_cast<uint32_t*>(&b0);
        packed.y = *reinterpret_cast<uint32_t*>(&b1);
        packed.z = *reinterpret_cast<uint32_t*>(&b2);
        packed.w = *reinterpret_cast<uint32_t*>(&b3);
        *reinterpret_cast<uint4*>(sm_dst + row * ROWB + c8 * 2) = packed;
    }
}

// Async-stage a 128 x 128 bf16 tile (contiguous 256B rows) into padded smem.
__device__ __forceinline__ void stage_A_async(uint32_t a_dst, const __nv_bfloat16* src) {
    const int tid = threadIdx.x;
    #pragma unroll
    for (int i = tid; i < 128 * 16; i += NTHREADS) {
        int row = i >> 4;
        int cb  = (i & 15) << 4;
        CP_ASYNC16(a_dst + row * ROWB + cb,
                   reinterpret_cast<const char*>(src) + row * 256 + cb);
    }
}

__global__ __launch_bounds__(NTHREADS, 1)
void colbert_fused_kernel(const float* __restrict__ qs,
                          const float* __restrict__ ps,
                          float* __restrict__ out) {
    extern __shared__ char sm[];
    __shared__ unsigned int s_target;
    __shared__ int s_last;

    const int c = blockIdx.x;
    const int half = blockIdx.y;
    const int cta = c * 2 + half;       // 0..127
    const int tid = threadIdx.x;
    const int lane = tid & 31;
    const int wid = tid >> 5;
    const int wr = wid & 3;             // row group: rows [wr*32, +32)
    const int wc = wid >> 2;            // col half within each 64-col nb block

    const uint32_t p_base = smem_u32(sm) + P_OFF;
    const uint32_t a_base = smem_u32(sm) + A_OFF;

    // ── Phase A: convert this CTA's 16-row slice of qs to bf16 global. ──
    {
        const float4* s4 = reinterpret_cast<const float4*>(qs) + ((size_t)cta * 256 + tid) * 2;
        float4 v0 = s4[0];
        float4 v1 = s4[1];
        __nv_bfloat162 b0 = __floats2bfloat162_rn(v0.x, v0.y);
        __nv_bfloat162 b1 = __floats2bfloat162_rn(v0.z, v0.w);
        __nv_bfloat162 b2 = __floats2bfloat162_rn(v1.x, v1.y);
        __nv_bfloat162 b3 = __floats2bfloat162_rn(v1.z, v1.w);
        uint4 packed;
        packed.x = *reinterpret_cast<uint32_t*>(&b0);
        packed.y = *reinterpret_cast<uint32_t*>(&b1);
        packed.z = *reinterpret_cast<uint32_t*>(&b2);
        packed.w = *reinterpret_cast<uint32_t*>(&b3);
        reinterpret_cast<uint4*>(g_qbf)[(size_t)cta * 256 + tid] = packed;
    }
    __threadfence();       // writer-side release for g_qbf (every thread)
    __syncthreads();
    if (tid == 0) {
        unsigned int old = atomicAdd(&g_qctr, 1u);
        s_target = (old / 128u) * 128u + 128u;   // epoch-safe across graph replays
    }

    // ── Phase B: stage the 512-token p half (fp32 -> bf16, disjoint per CTA). ──
    const float* pg = ps + ((size_t)c * 1024 + (size_t)half * HALF_TOK) * DIM;
    stage_bf16<HALF_TOK>(sm + P_OFF, pg);

    __syncthreads();
    if (tid == 0) {
        while (atomicAdd(&g_qctr, 0u) < s_target) { }
        __threadfence();
    }
    __syncthreads();

    stage_A_async(a_base, g_qbf);
    CP_COMMIT();

    // ldmatrix lane addressing.
    const uint32_t a_lane_off = (uint32_t)((lane & 15) * ROWB + (lane >> 4) * 16);
    const int bgrp = lane >> 3;
    const uint32_t b_lane_base = p_base
        + (uint32_t)(((bgrp >> 1) * 8 + (lane & 7)) * ROWB + (bgrp & 1) * 16)
        + (uint32_t)(wc * 32 * ROWB);   // this warp's 32-col half

    float* pout = g_part + (((size_t)(c * 2 + half)) * 2 + wc) * QROWS;

    // ── Phase C: 16 tiles of 128 q-rows vs 512 tokens. One barrier per tile. ──
    #pragma unroll 1
    for (int t = 0; t < NTILES; t++) {
        const uint32_t abuf = a_base + (uint32_t)(t & 1) * A_SZ;

        CP_WAIT0();
        __syncthreads();

        // Hoist A fragments: 2 m-tiles x 8 k-steps x 4 regs.
        uint32_t af[2][8][4];
        #pragma unroll
        for (int mt = 0; mt < 2; mt++) {
            #pragma unroll
            for (int ks = 0; ks < 8; ks++) {
                uint32_t addr = abuf + (uint32_t)((wr * 32 + mt * 16) * ROWB + ks * 32)
                              + a_lane_off;
                LDSM_X4(af[mt][ks][0], af[mt][ks][1], af[mt][ks][2], af[mt][ks][3], addr);
            }
        }

        if (t + 1 < NTILES) {
            stage_A_async(a_base + (uint32_t)((t + 1) & 1) * A_SZ,
                          g_qbf + (size_t)(t + 1) * 128 * DIM);
        }
        CP_COMMIT();

        float rm[2][2] = {{-3.0e38f, -3.0e38f}, {-3.0e38f, -3.0e38f}};

        // B-fragment double buffer: bfb[buf][8] = 4 n-frags x 2 regs.
        uint32_t bfb[2][8];
        {
            uint32_t b0 = b_lane_base;   // nb=0, ks=0
            LDSM_X4(bfb[0][0], bfb[0][1], bfb[0][2], bfb[0][3], b0);
            LDSM_X4(bfb[0][4], bfb[0][5], bfb[0][6], bfb[0][7], b0 + 16 * ROWB);
        }

        #pragma unroll 1
        for (int nb = 0; nb < 8; nb++) {
            float acc[2][4][4];
            #pragma unroll
            for (int mt = 0; mt < 2; mt++)
                #pragma unroll
                for (int nt = 0; nt < 4; nt++)
                    #pragma unroll
                    for (int i = 0; i < 4; i++) acc[mt][nt][i] = 0.0f;

            #pragma unroll
            for (int ks = 0; ks < 8; ks++) {
                const int cur = ks & 1;
                const int nxt = cur ^ 1;
                if (!(nb == 7 && ks == 7)) {
                    int knb = (ks == 7) ? nb + 1 : nb;
                    int kks = (ks == 7) ? 0 : ks + 1;
                    uint32_t b0 = b_lane_base + (uint32_t)(knb * 64 * ROWB + kks * 32);
                    LDSM_X4(bfb[nxt][0], bfb[nxt][1], bfb[nxt][2], bfb[nxt][3], b0);
                    LDSM_X4(bfb[nxt][4], bfb[nxt][5], bfb[nxt][6], bfb[nxt][7],
                            b0 + 16 * ROWB);
                }
                #pragma unroll
                for (int mt = 0; mt < 2; mt++)
                    #pragma unroll
                    for (int nt = 0; nt < 4; nt++)
                        MMA_16816(acc[mt][nt], af[mt][ks],
                                  bfb[cur][2 * nt], bfb[cur][2 * nt + 1]);
            }

            #pragma unroll
            for (int mt = 0; mt < 2; mt++)
                #pragma unroll
                for (int nt = 0; nt < 4; nt++) {
                    rm[mt][0] = fmaxf(rm[mt][0], fmaxf(acc[mt][nt][0], acc[mt][nt][1]));
                    rm[mt][1] = fmaxf(rm[mt][1], fmaxf(acc[mt][nt][2], acc[mt][nt][3]));
                }
        }

        // Reduce across the 4 lanes sharing each row; write partials straight
        // to global (no barrier, no smem).
        #pragma unroll
        for (int mt = 0; mt < 2; mt++)
            #pragma unroll
            for (int h = 0; h < 2; h++) {
                float v = rm[mt][h];
                v = fmaxf(v, __shfl_xor_sync(0xffffffffu, v, 1));
                v = fmaxf(v, __shfl_xor_sync(0xffffffffu, v, 2));
                if ((lane & 3) == 0) {
                    int qrow = t * 128 + wr * 32 + mt * 16 + h * 8 + (lane >> 2);
                    pout[qrow] = v;
                }
            }
    }

    // ── Phase D: last CTA of this c combines 4 partials + sums over n. ──
    __threadfence();       // writer-side release for g_part (every thread)
    __syncthreads();
    if (tid == 0) {
        unsigned int old = atomicAdd(&g_cctr[c], 1u);
        s_last = (old & 1u);
    }
    __syncthreads();
    if (s_last) {
        if (tid == 0) __threadfence();
        __syncthreads();
        const float* p0 = g_part + (((size_t)(c * 2 + 0)) * 2 + 0) * QROWS;
        const float* p1 = g_part + (((size_t)(c * 2 + 0)) * 2 + 1) * QROWS;
        const float* p2 = g_part + (((size_t)(c * 2 + 1)) * 2 + 0) * QROWS;
        const float* p3 = g_part + (((size_t)(c * 2 + 1)) * 2 + 1) * QROWS;
        #pragma unroll
        for (int bb = 0; bb < 8; bb++) {
            int b = wid + bb * 8;
            int qrow = b * 32 + lane;
            float m = fmaxf(fmaxf(p0[qrow], p1[qrow]), fmaxf(p2[qrow], p3[qrow]));
            #pragma unroll
            for (int o = 16; o; o >>= 1) m += __shfl_xor_sync(0xffffffffu, m, o);
            if (lane == 0) out[b * 64 + c] = m;
        }
    }
}

extern "C" void kernel_launch(void* const* d_in, const int* in_sizes, int n_in,
                              void* d_out, int out_size) {
    const float* qs = (const float*)d_in[0];   // (64, 32, 128)
    const float* ps = (const float*)d_in[1];   // (64, 1024, 128)
    float* out = (float*)d_out;                // (64, 64)

    cudaFuncSetAttribute(colbert_fused_kernel,
                         cudaFuncAttributeMaxDynamicSharedMemorySize, SM_TOTAL);
    dim3 grid(64, 2);
    colbert_fused_kernel<<<grid, NTHREADS, SM_TOTAL>>>(qs, ps, out);
}

// round 12
// speedup vs baseline: 1.1074x; 1.0209x over previous
#include <cuda_runtime.h>
#include <cuda_fp16.h>
#include <cstdint>

// ColBERT MaxSim via mma.sync fp16 HMMA (fp16 accumulate = 2x tensor rate).
//   scores[b,c] = sum_n max_s dot(qs[b,n,:], ps[c,s,:])
// qs: (64,32,128) fp32, ps: (64,1024,128) fp32, out: (64,64) fp32.
//
// grid (64 c, 2 half) = 128 CTAs, 1 CTA/SM, all resident. R11 base with
// fp16 inputs + fp16 accumulators (m16n8k16.f16.f16.f16.f16).

#define DIM 128
#define ROWB 272          // padded fp16 row: 136 halves = 272 B -> ldmatrix conflict-free
#define HALF_TOK 512
#define QROWS 2048        // 64 b * 32 n
#define NTILES 16
#define NTHREADS 256

#define P_OFF 0
#define A_OFF  (HALF_TOK * ROWB)            // 139264
#define A_SZ   (128 * ROWB)                 // 34816
#define SM_TOTAL (A_OFF + 2 * A_SZ)         // 208896

__device__ float g_part[64 * 2 * 2 * QROWS];   // [c][half][wc][qrow]
__device__ __half g_qf16[QROWS * DIM];
__device__ unsigned int g_qctr;        // monotonic across graph replays
__device__ unsigned int g_cctr[64];    // monotonic, parity = last of pair

__device__ __forceinline__ uint32_t smem_u32(const void* p) {
    uint32_t a;
    asm("{ .reg .u64 t; cvta.to.shared.u64 t, %1; cvt.u32.u64 %0, t; }" : "=r"(a) : "l"(p));
    return a;
}

#define LDSM_X4(r0, r1, r2, r3, addr) \
    asm volatile("ldmatrix.sync.aligned.m8n8.x4.shared.b16 {%0,%1,%2,%3}, [%4];" \
                 : "=r"(r0), "=r"(r1), "=r"(r2), "=r"(r3) : "r"(addr))

// fp16-accumulate HMMA: D,C are 2 regs (4 halves).
#define MMA_16816_F16(d, a, b0r, b1r) \
    asm volatile("mma.sync.aligned.m16n8k16.row.col.f16.f16.f16.f16 " \
                 "{%0,%1}, {%2,%3,%4,%5}, {%6,%7}, {%0,%1};" \
                 : "+r"((d)[0]), "+r"((d)[1]) \
                 : "r"((a)[0]), "r"((a)[1]), "r"((a)[2]), "r"((a)[3]), \
                   "r"(b0r), "r"(b1r))

#define CP_ASYNC16(dst, src) \
    asm volatile("cp.async.cg.shared.global [%0], [%1], 16;" :: "r"(dst), "l"(src) : "memory")
#define CP_COMMIT()  asm volatile("cp.async.commit_group;" ::: "memory")
#define CP_WAIT0()   asm volatile("cp.async.wait_group 0;" ::: "memory")

__device__ __forceinline__ uint32_t f2h2(float x, float y) {
    __half2 h = __floats2half2_rn(x, y);
    return *reinterpret_cast<uint32_t*>(&h);
}

// Convert a ROWS x 128 fp32 row-major tile into fp16 padded smem (stride ROWB bytes).
template<int ROWS>
__device__ __forceinline__ void stage_f16(char* sm_dst, const float* __restrict__ src) {
    const int tid = threadIdx.x;
    #pragma unroll 4
    for (int i = tid; i < ROWS * 16; i += NTHREADS) {
        int row = i >> 4;
        int c8  = (i & 15) << 3;
        const float4* s4 = reinterpret_cast<const float4*>(src + row * DIM + c8);
        float4 v0 = s4[0];
        float4 v1 = s4[1];
        uint4 packed;
        packed.x = f2h2(v0.x, v0.y);
        packed.y = f2h2(v0.z, v0.w);
        packed.z = f2h2(v1.x, v1.y);
        packed.w = f2h2(v1.z, v1.w);
        *reinterpret_cast<uint4*>(sm_dst + row * ROWB + c8 * 2) = packed;
    }
}

// Async-stage a 128 x 128 fp16 tile (contiguous 256B rows) into padded smem.
__device__ __forceinline__ void stage_A_async(uint32_t a_dst, const __half* src) {
    const int tid = threadIdx.x;
    #pragma unroll
    for (int i = tid; i < 128 * 16; i += NTHREADS) {
        int row = i >> 4;
        int cb  = (i & 15) << 4;
        CP_ASYNC16(a_dst + row * ROWB + cb,
                   reinterpret_cast<const char*>(src) + row * 256 + cb);
    }
}

__global__ __launch_bounds__(NTHREADS, 1)
void colbert_fused_kernel(const float* __restrict__ qs,
                          const float* __restrict__ ps,
                          float* __restrict__ out) {
    extern __shared__ char sm[];
    __shared__ unsigned int s_target;
    __shared__ int s_last;

    const int c = blockIdx.x;
    const int half_id = blockIdx.y;
    const int cta = c * 2 + half_id;    // 0..127
    const int tid = threadIdx.x;
    const int lane = tid & 31;
    const int wid = tid >> 5;
    const int wr = wid & 3;             // row group: rows [wr*32, +32)
    const int wc = wid >> 2;            // col half within each 64-col nb block

    const uint32_t p_base = smem_u32(sm) + P_OFF;
    const uint32_t a_base = smem_u32(sm) + A_OFF;

    // ── Phase A: convert this CTA's 16-row slice of qs to fp16 global. ──
    {
        const float4* s4 = reinterpret_cast<const float4*>(qs) + ((size_t)cta * 256 + tid) * 2;
        float4 v0 = s4[0];
        float4 v1 = s4[1];
        uint4 packed;
        packed.x = f2h2(v0.x, v0.y);
        packed.y = f2h2(v0.z, v0.w);
        packed.z = f2h2(v1.x, v1.y);
        packed.w = f2h2(v1.z, v1.w);
        reinterpret_cast<uint4*>(g_qf16)[(size_t)cta * 256 + tid] = packed;
    }
    __threadfence();       // writer-side release for g_qf16
    __syncthreads();
    if (tid == 0) {
        unsigned int old = atomicAdd(&g_qctr, 1u);
        s_target = (old / 128u) * 128u + 128u;   // epoch-safe across graph replays
    }

    // ── Phase B: stage the 512-token p half (fp32 -> fp16, disjoint per CTA). ──
    const float* pg = ps + ((size_t)c * 1024 + (size_t)half_id * HALF_TOK) * DIM;
    stage_f16<HALF_TOK>(sm + P_OFF, pg);

    __syncthreads();
    if (tid == 0) {
        while (atomicAdd(&g_qctr, 0u) < s_target) { }
        __threadfence();
    }
    __syncthreads();

    stage_A_async(a_base, g_qf16);
    CP_COMMIT();

    // ldmatrix lane addressing.
    const uint32_t a_lane_off = (uint32_t)((lane & 15) * ROWB + (lane >> 4) * 16);
    const int bgrp = lane >> 3;
    const uint32_t b_lane_base = p_base
        + (uint32_t)(((bgrp >> 1) * 8 + (lane & 7)) * ROWB + (bgrp & 1) * 16)
        + (uint32_t)(wc * 32 * ROWB);   // this warp's 32-col half

    float* pout = g_part + (((size_t)(c * 2 + half_id)) * 2 + wc) * QROWS;

    const __half2 NEG = __half2half2(__float2half(-60000.0f));
    const uint32_t NEGU = *reinterpret_cast<const uint32_t*>(&NEG);

    // ── Phase C: 16 tiles of 128 q-rows vs 512 tokens. One barrier per tile. ──
    #pragma unroll 1
    for (int t = 0; t < NTILES; t++) {
        const uint32_t abuf = a_base + (uint32_t)(t & 1) * A_SZ;

        CP_WAIT0();
        __syncthreads();

        // Hoist A fragments: 2 m-tiles x 8 k-steps x 4 regs.
        uint32_t af[2][8][4];
        #pragma unroll
        for (int mt = 0; mt < 2; mt++) {
            #pragma unroll
            for (int ks = 0; ks < 8; ks++) {
                uint32_t addr = abuf + (uint32_t)((wr * 32 + mt * 16) * ROWB + ks * 32)
                              + a_lane_off;
                LDSM_X4(af[mt][ks][0], af[mt][ks][1], af[mt][ks][2], af[mt][ks][3], addr);
            }
        }

        if (t + 1 < NTILES) {
            stage_A_async(a_base + (uint32_t)((t + 1) & 1) * A_SZ,
                          g_qf16 + (size_t)(t + 1) * 128 * DIM);
        }
        CP_COMMIT();

        // Running row maxes as half2 (cols packed pairwise): rm[mt][rowgrp].
        uint32_t rm[2][2] = {{NEGU, NEGU}, {NEGU, NEGU}};

        // B-fragment double buffer.
        uint32_t bfb[2][8];
        {
            uint32_t b0 = b_lane_base;   // nb=0, ks=0
            LDSM_X4(bfb[0][0], bfb[0][1], bfb[0][2], bfb[0][3], b0);
            LDSM_X4(bfb[0][4], bfb[0][5], bfb[0][6], bfb[0][7], b0 + 16 * ROWB);
        }

        #pragma unroll 1
        for (int nb = 0; nb < 8; nb++) {
            uint32_t acc[2][4][2];
            #pragma unroll
            for (int mt = 0; mt < 2; mt++)
                #pragma unroll
                for (int nt = 0; nt < 4; nt++) { acc[mt][nt][0] = 0u; acc[mt][nt][1] = 0u; }

            #pragma unroll
            for (int ks = 0; ks < 8; ks++) {
                const int cur = ks & 1;
                const int nxt = cur ^ 1;
                if (!(nb == 7 && ks == 7)) {
                    int knb = (ks == 7) ? nb + 1 : nb;
                    int kks = (ks == 7) ? 0 : ks + 1;
                    uint32_t b0 = b_lane_base + (uint32_t)(knb * 64 * ROWB + kks * 32);
                    LDSM_X4(bfb[nxt][0], bfb[nxt][1], bfb[nxt][2], bfb[nxt][3], b0);
                    LDSM_X4(bfb[nxt][4], bfb[nxt][5], bfb[nxt][6], bfb[nxt][7],
                            b0 + 16 * ROWB);
                }
                #pragma unroll
                for (int mt = 0; mt < 2; mt++)
                    #pragma unroll
                    for (int nt = 0; nt < 4; nt++)
                        MMA_16816_F16(acc[mt][nt], af[mt][ks],
                                      bfb[cur][2 * nt], bfb[cur][2 * nt + 1]);
            }

            #pragma unroll
            for (int mt = 0; mt < 2; mt++)
                #pragma unroll
                for (int nt = 0; nt < 4; nt++)
                    #pragma unroll
                    for (int h = 0; h < 2; h++) {
                        __half2 a = *reinterpret_cast<__half2*>(&acc[mt][nt][h]);
                        __half2 r = *reinterpret_cast<__half2*>(&rm[mt][h]);
                        r = __hmax2(r, a);
                        rm[mt][h] = *reinterpret_cast<uint32_t*>(&r);
                    }
        }

        // Reduce across the 4 lanes sharing each row; write partials to global.
        #pragma unroll
        for (int mt = 0; mt < 2; mt++)
            #pragma unroll
            for (int h = 0; h < 2; h++) {
                uint32_t vu = rm[mt][h];
                #pragma unroll
                for (int o = 1; o <= 2; o <<= 1) {
                    uint32_t other = __shfl_xor_sync(0xffffffffu, vu, o);
                    __half2 a = *reinterpret_cast<__half2*>(&vu);
                    __half2 b = *reinterpret_cast<__half2*>(&other);
                    __half2 m = __hmax2(a, b);
                    vu = *reinterpret_cast<uint32_t*>(&m);
                }
                if ((lane & 3) == 0) {
                    __half2 m = *reinterpret_cast<__half2*>(&vu);
                    float v = fmaxf(__half2float(__low2half(m)),
                                    __half2float(__high2half(m)));
                    int qrow = t * 128 + wr * 32 + mt * 16 + h * 8 + (lane >> 2);
                    pout[qrow] = v;
                }
            }
    }

    // ── Phase D: last CTA of this c combines 4 partials + sums over n. ──
    __threadfence();       // writer-side release for g_part
    __syncthreads();
    if (tid == 0) {
        unsigned int old = atomicAdd(&g_cctr[c], 1u);
        s_last = (old & 1u);
    }
    __syncthreads();
    if (s_last) {
        if (tid == 0) __threadfence();
        __syncthreads();
        const float* p0 = g_part + (((size_t)(c * 2 + 0)) * 2 + 0) * QROWS;
        const float* p1 = g_part + (((size_t)(c * 2 + 0)) * 2 + 1) * QROWS;
        const float* p2 = g_part + (((size_t)(c * 2 + 1)) * 2 + 0) * QROWS;
        const float* p3 = g_part + (((size_t)(c * 2 + 1)) * 2 + 1) * QROWS;
        #pragma unroll
        for (int bb = 0; bb < 8; bb++) {
            int b = wid + bb * 8;
            int qrow = b * 32 + lane;
            float m = fmaxf(fmaxf(p0[qrow], p1[qrow]), fmaxf(p2[qrow], p3[qrow]));
            #pragma unroll
            for (int o = 16; o; o >>= 1) m += __shfl_xor_sync(0xffffffffu, m, o);
            if (lane == 0) out[b * 64 + c] = m;
        }
    }
}

extern "C" void kernel_launch(void* const* d_in, const int* in_sizes, int n_in,
                              void* d_out, int out_size) {
    const float* qs = (const float*)d_in[0];   // (64, 32, 128)
    const float* ps = (const float*)d_in[1];   // (64, 1024, 128)
    float* out = (float*)d_out;                // (64, 64)

    cudaFuncSetAttribute(colbert_fused_kernel,
                         cudaFuncAttributeMaxDynamicSharedMemorySize, SM_TOTAL);
    dim3 grid(64, 2);
    colbert_fused_kernel<<<grid, NTHREADS, SM_TOTAL>>>(qs, ps, out);
}